// round 1
// baseline (speedup 1.0000x reference)
#include <cuda_runtime.h>
#include <math.h>

// ---------------------------------------------------------------------------
// GCNII layer:
//   theta = log(lamda/layer_idx + 1)
//   hi    = segment_sum(adj_vals * x[adj_cols], adj_rows)        (SpMM, COO row-sorted)
//   S     = (1-alpha)*hi + alpha*h0
//   out   = theta*(S @ W) + (1-theta)*S + x
// Folded:  M = theta*W + (1-theta)*I  (128x128);  out = S @ M + x
// ---------------------------------------------------------------------------

#define D 128                // feature dim (in == out == 128)
#define MAX_N 50001
#define TILE_ROWS 128
#define PAD 132              // smem row stride (multiple of 4 floats)
#define THREADS 512

__device__ int   g_row_ptr[MAX_N + 1];
__device__ float4 g_M4[D * (D / 4)];   // M, 16B-aligned

// --- CSR row offsets via binary search on sorted adj_rows ---
__global__ void build_rowptr_kernel(const int* __restrict__ rows, int E, int N) {
    int r = blockIdx.x * blockDim.x + threadIdx.x;
    if (r > N) return;
    int lo = 0, hi = E;
    while (lo < hi) {
        int mid = (lo + hi) >> 1;
        if (rows[mid] < r) lo = mid + 1; else hi = mid;
    }
    g_row_ptr[r] = lo;
}

// --- M = theta*W + (1-theta)*I ---
__global__ void build_M_kernel(const float* __restrict__ W,
                               const float* __restrict__ lamda_p,
                               const int* __restrict__ li_p) {
    int i = blockIdx.x * blockDim.x + threadIdx.x;
    if (i >= D * D) return;
    float lif = 2.0f;
    if (li_p) {
        int raw = li_p[0];
        // layer_idx may arrive as int32 or as float bits; disambiguate.
        lif = (raw >= 1 && raw <= 1000000) ? (float)raw : __int_as_float(raw);
    }
    float theta = logf(lamda_p[0] / lif + 1.0f);
    float m = theta * W[i];
    if ((i >> 7) == (i & 127)) m += 1.0f - theta;   // diagonal
    ((float*)g_M4)[i] = m;
}

#define FMA4(acc, v, p) do {                      \
    (acc).x = fmaf((v), (p).x, (acc).x);          \
    (acc).y = fmaf((v), (p).y, (acc).y);          \
    (acc).z = fmaf((v), (p).z, (acc).z);          \
    (acc).w = fmaf((v), (p).w, (acc).w); } while (0)

// --- fused: SpMM tile -> smem, then GEMM tile vs M in smem, + x residual ---
__global__ void __launch_bounds__(THREADS, 1)
gcn_fused_kernel(const float* __restrict__ x,
                 const float* __restrict__ h0,
                 const int*   __restrict__ cols,
                 const float* __restrict__ vals,
                 const float* __restrict__ alpha_p,
                 float* __restrict__ out,
                 int N)
{
    extern __shared__ float sm[];
    float* As = sm;                 // support tile [TILE_ROWS][PAD], row-major
    float* Ms = sm + TILE_ROWS * PAD; // M [128][PAD]

    const float4* X4 = (const float4*)x;
    const float4* H4 = (const float4*)h0;

    const int tid = threadIdx.x;
    const int rowBase = blockIdx.x * TILE_ROWS;

    // ---- stage M into smem (overlaps with SpMM loads) ----
    for (int i = tid; i < D * (D / 4); i += THREADS) {
        int k = i >> 5, c4 = i & 31;
        *(float4*)&Ms[k * PAD + c4 * 4] = g_M4[i];
    }

    // ---- phase 1: SpMM + alpha-combine, one warp per row ----
    const int warp = tid >> 5;
    const int lane = tid & 31;
    const float alpha = alpha_p[0];
    const float oma = 1.0f - alpha;

    for (int rr = warp; rr < TILE_ROWS; rr += (THREADS / 32)) {
        int r = rowBase + rr;
        float4 acc = make_float4(0.f, 0.f, 0.f, 0.f);
        if (r < N) {
            int e   = g_row_ptr[r];
            int end = g_row_ptr[r + 1];
            // unroll by 4 for MLP on the L2-resident x gathers
            for (; e + 4 <= end; e += 4) {
                int   c0 = cols[e],     c1 = cols[e + 1];
                int   c2 = cols[e + 2], c3 = cols[e + 3];
                float v0 = vals[e],     v1 = vals[e + 1];
                float v2 = vals[e + 2], v3 = vals[e + 3];
                float4 p0 = X4[(size_t)c0 * 32 + lane];
                float4 p1 = X4[(size_t)c1 * 32 + lane];
                float4 p2 = X4[(size_t)c2 * 32 + lane];
                float4 p3 = X4[(size_t)c3 * 32 + lane];
                FMA4(acc, v0, p0);
                FMA4(acc, v1, p1);
                FMA4(acc, v2, p2);
                FMA4(acc, v3, p3);
            }
            for (; e < end; ++e) {
                int c = cols[e]; float v = vals[e];
                float4 p = X4[(size_t)c * 32 + lane];
                FMA4(acc, v, p);
            }
            float4 h = H4[(size_t)r * 32 + lane];
            acc.x = fmaf(oma, acc.x, alpha * h.x);
            acc.y = fmaf(oma, acc.y, alpha * h.y);
            acc.z = fmaf(oma, acc.z, alpha * h.z);
            acc.w = fmaf(oma, acc.w, alpha * h.w);
        }
        // conflict-free STS.128 (contiguous 512B per warp)
        *(float4*)&As[rr * PAD + lane * 4] = acc;
    }
    __syncthreads();

    // ---- phase 2: out[tile] = As @ M + x ----
    // 512 threads = 32 row-groups x 16 col-groups; each thread: 4 rows x 8 cols
    const int tx = tid & 15;   // col group
    const int ty = tid >> 4;   // row group (0..31)
    const int r0 = ty * 4;
    const int c0 = tx * 8;

    float acc[4][8];
    #pragma unroll
    for (int i = 0; i < 4; ++i)
        #pragma unroll
        for (int j = 0; j < 8; ++j) acc[i][j] = 0.f;

    #pragma unroll 2
    for (int k = 0; k < D; k += 4) {
        float4 a[4];
        #pragma unroll
        for (int i = 0; i < 4; ++i)
            a[i] = *(const float4*)&As[(r0 + i) * PAD + k];
        float4 b0[4], b1[4];
        #pragma unroll
        for (int j = 0; j < 4; ++j) {
            b0[j] = *(const float4*)&Ms[(k + j) * PAD + c0];
            b1[j] = *(const float4*)&Ms[(k + j) * PAD + c0 + 4];
        }
        #pragma unroll
        for (int j = 0; j < 4; ++j) {
            #pragma unroll
            for (int i = 0; i < 4; ++i) {
                const float* ap = (const float*)&a[i];
                float av = ap[j];
                acc[i][0] = fmaf(av, b0[j].x, acc[i][0]);
                acc[i][1] = fmaf(av, b0[j].y, acc[i][1]);
                acc[i][2] = fmaf(av, b0[j].z, acc[i][2]);
                acc[i][3] = fmaf(av, b0[j].w, acc[i][3]);
                acc[i][4] = fmaf(av, b1[j].x, acc[i][4]);
                acc[i][5] = fmaf(av, b1[j].y, acc[i][5]);
                acc[i][6] = fmaf(av, b1[j].z, acc[i][6]);
                acc[i][7] = fmaf(av, b1[j].w, acc[i][7]);
            }
        }
    }

    // ---- epilogue: + x residual, STG.128 ----
    float4* O4 = (float4*)out;
    #pragma unroll
    for (int i = 0; i < 4; ++i) {
        int r = rowBase + r0 + i;
        if (r < N) {
            size_t base = (size_t)r * 32 + tx * 2;
            float4 xa = X4[base];
            float4 xb = X4[base + 1];
            float4 oa, ob;
            oa.x = acc[i][0] + xa.x; oa.y = acc[i][1] + xa.y;
            oa.z = acc[i][2] + xa.z; oa.w = acc[i][3] + xa.w;
            ob.x = acc[i][4] + xb.x; ob.y = acc[i][5] + xb.y;
            ob.z = acc[i][6] + xb.z; ob.w = acc[i][7] + xb.w;
            O4[base]     = oa;
            O4[base + 1] = ob;
        }
    }
}

extern "C" void kernel_launch(void* const* d_in, const int* in_sizes, int n_in,
                              void* d_out, int out_size) {
    const float* x      = (const float*)d_in[0];
    const float* h0     = (const float*)d_in[1];
    const float* W      = (const float*)d_in[2];
    const float* lamda  = (const float*)d_in[3];
    const float* alpha  = (const float*)d_in[4];
    const int*   arows  = (const int*)d_in[5];
    const int*   acols  = (const int*)d_in[6];
    const float* avals  = (const float*)d_in[7];
    const int*   li     = (n_in > 8) ? (const int*)d_in[8] : nullptr;

    const int N = in_sizes[0] / D;
    const int E = in_sizes[5];

    build_rowptr_kernel<<<(N + 1 + 255) / 256, 256>>>(arows, E, N);
    build_M_kernel<<<(D * D + 255) / 256, 256>>>(W, lamda, li);

    size_t smem = (size_t)2 * TILE_ROWS * PAD * sizeof(float);  // 135168 B
    cudaFuncSetAttribute(gcn_fused_kernel,
                         cudaFuncAttributeMaxDynamicSharedMemorySize, (int)smem);
    gcn_fused_kernel<<<(N + TILE_ROWS - 1) / TILE_ROWS, THREADS, smem>>>(
        x, h0, acols, avals, alpha, (float*)d_out, N);
}

// round 3
// speedup vs baseline: 1.2067x; 1.2067x over previous
#include <cuda_runtime.h>
#include <math.h>
#include <stdint.h>

// GCNII layer, folded:  M = theta*W + (1-theta)*I ;  out = S @ M + x
//   S = (1-alpha)*segment_sum(vals*x[cols], rows) + alpha*h0
// Per 128-row tile (one block):
//   phase 0: in-block rowptr binary searches + stage Mt(hi/lo bf16) to smem
//   phase 1: warp-per-row SpMM gather, S split to bf16 hi/lo in smem
//   phase 2: mma.sync m16n8k16 bf16, 3 passes (hi*hi + hi*lo + lo*hi), fp32 acc
//   epilogue: + x residual -> out

#define D 128
#define TILE_ROWS 128
#define THREADS 512
#define NWARP 16
#define SSTRB 272            // smem row stride bytes (136 bf16): 4-bank skew, LDSM conflict-free

// Mt in bf16 hi/lo pairs, row-major [n][k/2] (u32 = 2 bf16 along k)
__device__ uint32_t g_Bhi[D * D / 2];
__device__ uint32_t g_Blo[D * D / 2];

// smem map (bytes)
#define SM_RPTR  0
#define SM_SHI   1024
#define SM_SLO   (1024 + 34816)
#define SM_BHI   (1024 + 2 * 34816)
#define SM_BLO   (1024 + 3 * 34816)
#define SM_TOTAL (1024 + 4 * 34816)   // 140288

__device__ __forceinline__ uint32_t smem_u32(const void* p) {
    uint32_t a;
    asm("{ .reg .u64 t; cvta.to.shared.u64 t, %1; cvt.u32.u64 %0, t; }" : "=r"(a) : "l"(p));
    return a;
}
__device__ __forceinline__ uint32_t pack_bf16x2(float f_lo, float f_hi) {
    uint32_t r;  // upper half <- first operand
    asm("cvt.rn.bf16x2.f32 %0, %1, %2;" : "=r"(r) : "f"(f_hi), "f"(f_lo));
    return r;
}

#define LDSM_X4(r, addr)                                                      \
    asm volatile("ldmatrix.sync.aligned.m8n8.x4.shared.b16 {%0,%1,%2,%3}, [%4];" \
                 : "=r"((r)[0]), "=r"((r)[1]), "=r"((r)[2]), "=r"((r)[3])     \
                 : "r"(addr))

#define MMA(c, a, bb0, bb1)                                                   \
    asm volatile("mma.sync.aligned.m16n8k16.row.col.f32.bf16.bf16.f32 "       \
                 "{%0,%1,%2,%3}, {%4,%5,%6,%7}, {%8,%9}, {%0,%1,%2,%3};"      \
                 : "+f"((c)[0]), "+f"((c)[1]), "+f"((c)[2]), "+f"((c)[3])     \
                 : "r"((a)[0]), "r"((a)[1]), "r"((a)[2]), "r"((a)[3]),        \
                   "r"(bb0), "r"(bb1))

// ---------------- prolog: Mt = (theta*W + (1-theta)*I)^T as bf16 hi/lo -----
__global__ void prolog_kernel(const float* __restrict__ W,
                              const float* __restrict__ lamda_p,
                              const int* __restrict__ li_p) {
    int t = blockIdx.x * blockDim.x + threadIdx.x;
    if (t >= D * D / 2) return;
    float lif = 2.0f;
    if (li_p) {
        int raw = li_p[0];
        lif = (raw >= 1 && raw <= 1000000) ? (float)raw : __int_as_float(raw);
    }
    float theta = logf(lamda_p[0] / lif + 1.0f);
    int n = t >> 6;
    int k = (t & 63) * 2;
    float v0 = theta * W[(size_t)k * D + n]       + ((n == k)     ? (1.0f - theta) : 0.f);
    float v1 = theta * W[(size_t)(k + 1) * D + n] + ((n == k + 1) ? (1.0f - theta) : 0.f);
    uint32_t hi = pack_bf16x2(v0, v1);
    float r0 = v0 - __uint_as_float(hi << 16);
    float r1 = v1 - __uint_as_float(hi & 0xffff0000u);
    g_Bhi[t] = hi;
    g_Blo[t] = pack_bf16x2(r0, r1);
}

// ---------------- fused main kernel ----------------
__global__ void __launch_bounds__(THREADS, 1)
gcn_fused_kernel(const float* __restrict__ x,
                 const float* __restrict__ h0,
                 const int*   __restrict__ rows,
                 const int*   __restrict__ cols,
                 const float* __restrict__ vals,
                 const float* __restrict__ alpha_p,
                 float* __restrict__ out,
                 int N, int E)
{
    extern __shared__ char smem[];
    int* s_rptr = (int*)smem;
    const uint32_t smb = smem_u32(smem);
    const int tid  = threadIdx.x;
    const int wid  = tid >> 5;
    const int lane = tid & 31;
    const int rowBase = blockIdx.x * TILE_ROWS;

    // ---- phase 0a: per-block rowptr boundaries (first edge with row >= r) ----
    if (tid <= TILE_ROWS) {
        int r = rowBase + tid;
        int lo = 0, hi = E;
        while (lo < hi) {
            int m = (lo + hi) >> 1;
            if (__ldg(&rows[m]) < r) lo = m + 1; else hi = m;
        }
        s_rptr[tid] = lo;
    }
    // ---- phase 0b: stage Mt hi/lo into padded smem rows ----
    {
        const float4* sh = (const float4*)g_Bhi;
        const float4* sl = (const float4*)g_Blo;
        #pragma unroll
        for (int i = tid; i < 2048; i += THREADS) {      // 2048 float4 per array
            int row = i >> 4, c16 = i & 15;              // 16 x 16B chunks per 256B row
            *(float4*)(smem + SM_BHI + row * SSTRB + c16 * 16) = sh[i];
            *(float4*)(smem + SM_BLO + row * SSTRB + c16 * 16) = sl[i];
        }
    }
    __syncthreads();

    // ---- phase 1: SpMM + alpha-combine, one warp per row; split to bf16 hi/lo
    const float alpha = alpha_p[0];
    const float oma = 1.0f - alpha;
    const float4* X4 = (const float4*)x;
    const float4* H4 = (const float4*)h0;

    for (int rr = wid; rr < TILE_ROWS; rr += NWARP) {
        int r = rowBase + rr;
        float4 acc = make_float4(0.f, 0.f, 0.f, 0.f);
        if (r < N) {
            int e   = s_rptr[rr];
            int end = s_rptr[rr + 1];
            for (; e + 4 <= end; e += 4) {
                int   c0 = cols[e],     c1 = cols[e + 1];
                int   c2 = cols[e + 2], c3 = cols[e + 3];
                float v0 = vals[e],     v1 = vals[e + 1];
                float v2 = vals[e + 2], v3 = vals[e + 3];
                float4 p0 = X4[(size_t)c0 * 32 + lane];
                float4 p1 = X4[(size_t)c1 * 32 + lane];
                float4 p2 = X4[(size_t)c2 * 32 + lane];
                float4 p3 = X4[(size_t)c3 * 32 + lane];
                acc.x = fmaf(v0, p0.x, acc.x); acc.y = fmaf(v0, p0.y, acc.y);
                acc.z = fmaf(v0, p0.z, acc.z); acc.w = fmaf(v0, p0.w, acc.w);
                acc.x = fmaf(v1, p1.x, acc.x); acc.y = fmaf(v1, p1.y, acc.y);
                acc.z = fmaf(v1, p1.z, acc.z); acc.w = fmaf(v1, p1.w, acc.w);
                acc.x = fmaf(v2, p2.x, acc.x); acc.y = fmaf(v2, p2.y, acc.y);
                acc.z = fmaf(v2, p2.z, acc.z); acc.w = fmaf(v2, p2.w, acc.w);
                acc.x = fmaf(v3, p3.x, acc.x); acc.y = fmaf(v3, p3.y, acc.y);
                acc.z = fmaf(v3, p3.z, acc.z); acc.w = fmaf(v3, p3.w, acc.w);
            }
            for (; e < end; ++e) {
                int c = cols[e]; float v = vals[e];
                float4 p = X4[(size_t)c * 32 + lane];
                acc.x = fmaf(v, p.x, acc.x); acc.y = fmaf(v, p.y, acc.y);
                acc.z = fmaf(v, p.z, acc.z); acc.w = fmaf(v, p.w, acc.w);
            }
            float4 h = H4[(size_t)r * 32 + lane];
            acc.x = fmaf(oma, acc.x, alpha * h.x);
            acc.y = fmaf(oma, acc.y, alpha * h.y);
            acc.z = fmaf(oma, acc.z, alpha * h.z);
            acc.w = fmaf(oma, acc.w, alpha * h.w);
        }
        uint32_t h01 = pack_bf16x2(acc.x, acc.y);
        uint32_t h23 = pack_bf16x2(acc.z, acc.w);
        float l0 = acc.x - __uint_as_float(h01 << 16);
        float l1 = acc.y - __uint_as_float(h01 & 0xffff0000u);
        float l2 = acc.z - __uint_as_float(h23 << 16);
        float l3 = acc.w - __uint_as_float(h23 & 0xffff0000u);
        uint32_t q01 = pack_bf16x2(l0, l1);
        uint32_t q23 = pack_bf16x2(l2, l3);
        uint32_t off = (uint32_t)(rr * SSTRB + lane * 8);
        asm volatile("st.shared.v2.b32 [%0], {%1, %2};"
                     :: "r"(smb + SM_SHI + off), "r"(h01), "r"(h23) : "memory");
        asm volatile("st.shared.v2.b32 [%0], {%1, %2};"
                     :: "r"(smb + SM_SLO + off), "r"(q01), "r"(q23) : "memory");
    }
    __syncthreads();

    // ---- phase 2: 16 warps x (32x32) warp tiles; mma.sync bf16, 3 passes ----
    const int wm = (wid & 3) * 32;     // warp row block
    const int wn = (wid >> 2) * 32;    // warp col block
    const int quad = lane >> 3;
    const int l7 = lane & 7;
    // A frag ldmatrix lane addressing: matrices (m0-7,k0-7),(m8-15,k0-7),(m0-7,k8-15),(m8-15,k8-15)
    const uint32_t aoff = (uint32_t)((((quad & 1) * 8) + l7) * SSTRB + (quad >> 1) * 16);
    // B frag x4 covers 2 n-tiles: (n0-7,k0-7),(n0-7,k8-15),(n8-15,k0-7),(n8-15,k8-15)
    const uint32_t boff = (uint32_t)((((quad >> 1) * 8) + l7) * SSTRB + (quad & 1) * 16);

    float acc[2][4][4];
    #pragma unroll
    for (int i = 0; i < 2; ++i)
        #pragma unroll
        for (int j = 0; j < 4; ++j)
            #pragma unroll
            for (int k = 0; k < 4; ++k) acc[i][j][k] = 0.f;

    #pragma unroll
    for (int pass = 0; pass < 3; ++pass) {
        const uint32_t Ab = smb + (pass == 2 ? SM_SLO : SM_SHI) + (uint32_t)(wm * SSTRB) + aoff;
        const uint32_t Bb = smb + (pass == 1 ? SM_BLO : SM_BHI) + (uint32_t)(wn * SSTRB) + boff;
        #pragma unroll
        for (int ks = 0; ks < 8; ++ks) {
            uint32_t a0[4], a1[4], b01[4], b23[4];
            LDSM_X4(a0, Ab + ks * 32);
            LDSM_X4(a1, Ab + ks * 32 + 16 * SSTRB);
            LDSM_X4(b01, Bb + ks * 32);
            LDSM_X4(b23, Bb + ks * 32 + 16 * SSTRB);
            MMA(acc[0][0], a0, b01[0], b01[1]);
            MMA(acc[0][1], a0, b01[2], b01[3]);
            MMA(acc[0][2], a0, b23[0], b23[1]);
            MMA(acc[0][3], a0, b23[2], b23[3]);
            MMA(acc[1][0], a1, b01[0], b01[1]);
            MMA(acc[1][1], a1, b01[2], b01[3]);
            MMA(acc[1][2], a1, b23[0], b23[1]);
            MMA(acc[1][3], a1, b23[2], b23[3]);
        }
    }

    // ---- epilogue: + x residual ----
    const int g = lane >> 2, tig = lane & 3;
    #pragma unroll
    for (int mt = 0; mt < 2; ++mt) {
        #pragma unroll
        for (int half = 0; half < 2; ++half) {
            int r = rowBase + wm + mt * 16 + half * 8 + g;
            if (r < N) {
                const float2* Xr = (const float2*)x + (size_t)r * 64;
                float2* Or = (float2*)out + (size_t)r * 64;
                #pragma unroll
                for (int nt = 0; nt < 4; ++nt) {
                    int cp = (wn >> 1) + nt * 4 + tig;   // float2 index
                    float2 xv = Xr[cp];
                    float2 o;
                    o.x = acc[mt][nt][half * 2 + 0] + xv.x;
                    o.y = acc[mt][nt][half * 2 + 1] + xv.y;
                    Or[cp] = o;
                }
            }
        }
    }
}

extern "C" void kernel_launch(void* const* d_in, const int* in_sizes, int n_in,
                              void* d_out, int out_size) {
    const float* x     = (const float*)d_in[0];
    const float* h0    = (const float*)d_in[1];
    const float* W     = (const float*)d_in[2];
    const float* lamda = (const float*)d_in[3];
    const float* alpha = (const float*)d_in[4];
    const int*   arows = (const int*)d_in[5];
    const int*   acols = (const int*)d_in[6];
    const float* avals = (const float*)d_in[7];
    const int*   li    = (n_in > 8) ? (const int*)d_in[8] : nullptr;

    const int N = in_sizes[0] / D;
    const int E = in_sizes[5];

    prolog_kernel<<<(D * D / 2 + 511) / 512, 512>>>(W, lamda, li);

    cudaFuncSetAttribute(gcn_fused_kernel,
                         cudaFuncAttributeMaxDynamicSharedMemorySize, SM_TOTAL);
    gcn_fused_kernel<<<(N + TILE_ROWS - 1) / TILE_ROWS, THREADS, SM_TOTAL>>>(
        x, h0, arows, acols, avals, alpha, (float*)d_out, N, E);
}

// round 6
// speedup vs baseline: 1.3491x; 1.1180x over previous
#include <cuda_runtime.h>
#include <math.h>
#include <stdint.h>

// GCNII layer, folded:  M = theta*W + (1-theta)*I ;  out = S @ M + x
//   S = (1-alpha)*segment_sum(vals*x[cols], rows) + alpha*h0
// Per 128-row tile (one block):
//   phase 0: in-block rowptr binary searches; stage Mt(hi/lo bf16) to smem;
//            stage the tile's contiguous edge range (cols+vals) to smem
//   phase 1: warp-per-row SpMM gather (addresses from smem, 8-wide MLP),
//            S split to bf16 hi/lo in smem
//   phase 2: mma.sync m16n8k16 bf16, 3 passes (hi*hi + hi*lo + lo*hi), fp32 acc
//   epilogue: + x residual -> out

#define D 128
#define TILE_ROWS 128
#define THREADS 512
#define NWARP 16
#define SSTRB 272            // smem row stride bytes: 4-bank skew, LDSM conflict-free
#define EDGE_CAP 3072        // staged edges per tile (mean 2048, std ~45 -> >20 sigma)

__device__ uint32_t g_Bhi[D * D / 2];
__device__ uint32_t g_Blo[D * D / 2];

// smem map (bytes)
#define SM_RPTR  0
#define SM_SHI   1024
#define SM_SLO   (1024 + 34816)
#define SM_BHI   (1024 + 2 * 34816)
#define SM_BLO   (1024 + 3 * 34816)
#define SM_ECOL  (1024 + 4 * 34816)              // 140288
#define SM_EVAL  (SM_ECOL + EDGE_CAP * 4)        // 152576
#define SM_TOTAL (SM_EVAL + EDGE_CAP * 4)        // 164864

__device__ __forceinline__ uint32_t smem_u32(const void* p) {
    uint32_t a;
    asm("{ .reg .u64 t; cvta.to.shared.u64 t, %1; cvt.u32.u64 %0, t; }" : "=r"(a) : "l"(p));
    return a;
}
__device__ __forceinline__ uint32_t pack_bf16x2(float f_lo, float f_hi) {
    uint32_t r;  // upper half <- first operand
    asm("cvt.rn.bf16x2.f32 %0, %1, %2;" : "=r"(r) : "f"(f_hi), "f"(f_lo));
    return r;
}

#define LDSM_X4(r, addr)                                                      \
    asm volatile("ldmatrix.sync.aligned.m8n8.x4.shared.b16 {%0,%1,%2,%3}, [%4];" \
                 : "=r"((r)[0]), "=r"((r)[1]), "=r"((r)[2]), "=r"((r)[3])     \
                 : "r"(addr))

#define MMA(c, a, bb0, bb1)                                                   \
    asm volatile("mma.sync.aligned.m16n8k16.row.col.f32.bf16.bf16.f32 "       \
                 "{%0,%1,%2,%3}, {%4,%5,%6,%7}, {%8,%9}, {%0,%1,%2,%3};"      \
                 : "+f"((c)[0]), "+f"((c)[1]), "+f"((c)[2]), "+f"((c)[3])     \
                 : "r"((a)[0]), "r"((a)[1]), "r"((a)[2]), "r"((a)[3]),        \
                   "r"(bb0), "r"(bb1))

#define GFMA(acc, v, p) do {                                                  \
    (acc).x = fmaf((v), (p).x, (acc).x); (acc).y = fmaf((v), (p).y, (acc).y); \
    (acc).z = fmaf((v), (p).z, (acc).z); (acc).w = fmaf((v), (p).w, (acc).w); } while (0)

// ---------------- prolog: Mt = (theta*W + (1-theta)*I)^T as bf16 hi/lo -----
__global__ void prolog_kernel(const float* __restrict__ W,
                              const float* __restrict__ lamda_p,
                              const int* __restrict__ li_p) {
    int t = blockIdx.x * blockDim.x + threadIdx.x;
    if (t >= D * D / 2) return;
    float lif = 2.0f;
    if (li_p) {
        int raw = li_p[0];
        lif = (raw >= 1 && raw <= 1000000) ? (float)raw : __int_as_float(raw);
    }
    float theta = logf(lamda_p[0] / lif + 1.0f);
    int n = t >> 6;
    int k = (t & 63) * 2;
    float v0 = theta * W[(size_t)k * D + n]       + ((n == k)     ? (1.0f - theta) : 0.f);
    float v1 = theta * W[(size_t)(k + 1) * D + n] + ((n == k + 1) ? (1.0f - theta) : 0.f);
    uint32_t hi = pack_bf16x2(v0, v1);
    float r0 = v0 - __uint_as_float(hi << 16);
    float r1 = v1 - __uint_as_float(hi & 0xffff0000u);
    g_Bhi[t] = hi;
    g_Blo[t] = pack_bf16x2(r0, r1);
}

// ---------------- fused main kernel ----------------
__global__ void __launch_bounds__(THREADS, 1)
gcn_fused_kernel(const float* __restrict__ x,
                 const float* __restrict__ h0,
                 const int*   __restrict__ rows,
                 const int*   __restrict__ cols,
                 const float* __restrict__ vals,
                 const float* __restrict__ alpha_p,
                 float* __restrict__ out,
                 int N, int E)
{
    extern __shared__ char smem[];
    int* s_rptr = (int*)smem;
    const uint32_t smb = smem_u32(smem);
    const int tid  = threadIdx.x;
    const int wid  = tid >> 5;
    const int lane = tid & 31;
    const int rowBase = blockIdx.x * TILE_ROWS;

    // ---- phase 0a: per-block rowptr boundaries ----
    if (tid <= TILE_ROWS) {
        int r = rowBase + tid;
        int lo = 0, hi = E;
        while (lo < hi) {
            int m = (lo + hi) >> 1;
            if (__ldg(&rows[m]) < r) lo = m + 1; else hi = m;
        }
        s_rptr[tid] = lo;
    }
    // ---- phase 0b: stage Mt hi/lo into padded smem rows ----
    {
        const float4* sh = (const float4*)g_Bhi;
        const float4* sl = (const float4*)g_Blo;
        #pragma unroll
        for (int i = tid; i < 2048; i += THREADS) {
            int row = i >> 4, c16 = i & 15;
            *(float4*)(smem + SM_BHI + row * SSTRB + c16 * 16) = sh[i];
            *(float4*)(smem + SM_BLO + row * SSTRB + c16 * 16) = sl[i];
        }
    }
    __syncthreads();

    // ---- phase 0c: stage this tile's edge range into smem (pure streams) ----
    const int e0 = s_rptr[0];
    const int e1 = s_rptr[TILE_ROWS];
    const int staged = min(e1 - e0, EDGE_CAP);
    {
        int* s_ecol = (int*)(smem + SM_ECOL);
        for (int i = tid; i < staged; i += THREADS) s_ecol[i] = cols[e0 + i];
        float* s_eval = (float*)(smem + SM_EVAL);
        for (int i = tid; i < staged; i += THREADS) s_eval[i] = vals[e0 + i];
    }
    __syncthreads();

    // ---- phase 1: SpMM + alpha-combine, one warp per row ----
    const float alpha = alpha_p[0];
    const float oma = 1.0f - alpha;
    const float4* X4 = (const float4*)x;
    const float4* H4 = (const float4*)h0;
    const int* s_ecol = (const int*)(smem + SM_ECOL);
    const float* s_eval = (const float*)(smem + SM_EVAL);

    for (int rr = wid; rr < TILE_ROWS; rr += NWARP) {
        int r = rowBase + rr;
        float4 acc = make_float4(0.f, 0.f, 0.f, 0.f);
        if (r < N) {
            int eb = s_rptr[rr]     - e0;
            int ee = s_rptr[rr + 1] - e0;
            if (ee <= staged) {
                // smem-addressed gather, 8-wide MLP
                int j = eb;
                for (; j + 8 <= ee; j += 8) {
                    int   c0 = s_ecol[j],     c1 = s_ecol[j + 1];
                    int   c2 = s_ecol[j + 2], c3 = s_ecol[j + 3];
                    int   c4 = s_ecol[j + 4], c5 = s_ecol[j + 5];
                    int   c6 = s_ecol[j + 6], c7 = s_ecol[j + 7];
                    float4 p0 = X4[(size_t)c0 * 32 + lane];
                    float4 p1 = X4[(size_t)c1 * 32 + lane];
                    float4 p2 = X4[(size_t)c2 * 32 + lane];
                    float4 p3 = X4[(size_t)c3 * 32 + lane];
                    float4 p4 = X4[(size_t)c4 * 32 + lane];
                    float4 p5 = X4[(size_t)c5 * 32 + lane];
                    float4 p6 = X4[(size_t)c6 * 32 + lane];
                    float4 p7 = X4[(size_t)c7 * 32 + lane];
                    float v0 = s_eval[j],     v1 = s_eval[j + 1];
                    float v2 = s_eval[j + 2], v3 = s_eval[j + 3];
                    float v4 = s_eval[j + 4], v5 = s_eval[j + 5];
                    float v6 = s_eval[j + 6], v7 = s_eval[j + 7];
                    GFMA(acc, v0, p0); GFMA(acc, v1, p1);
                    GFMA(acc, v2, p2); GFMA(acc, v3, p3);
                    GFMA(acc, v4, p4); GFMA(acc, v5, p5);
                    GFMA(acc, v6, p6); GFMA(acc, v7, p7);
                }
                if (j + 4 <= ee) {
                    int   c0 = s_ecol[j],     c1 = s_ecol[j + 1];
                    int   c2 = s_ecol[j + 2], c3 = s_ecol[j + 3];
                    float4 p0 = X4[(size_t)c0 * 32 + lane];
                    float4 p1 = X4[(size_t)c1 * 32 + lane];
                    float4 p2 = X4[(size_t)c2 * 32 + lane];
                    float4 p3 = X4[(size_t)c3 * 32 + lane];
                    float v0 = s_eval[j],     v1 = s_eval[j + 1];
                    float v2 = s_eval[j + 2], v3 = s_eval[j + 3];
                    GFMA(acc, v0, p0); GFMA(acc, v1, p1);
                    GFMA(acc, v2, p2); GFMA(acc, v3, p3);
                    j += 4;
                }
                for (; j < ee; ++j) {
                    int c = s_ecol[j]; float v = s_eval[j];
                    float4 p = X4[(size_t)c * 32 + lane];
                    GFMA(acc, v, p);
                }
            } else {
                // gmem fallback (tile exceeded EDGE_CAP)
                int e = eb + e0, end = ee + e0;
                for (; e + 4 <= end; e += 4) {
                    int   c0 = cols[e],     c1 = cols[e + 1];
                    int   c2 = cols[e + 2], c3 = cols[e + 3];
                    float v0 = vals[e],     v1 = vals[e + 1];
                    float v2 = vals[e + 2], v3 = vals[e + 3];
                    float4 p0 = X4[(size_t)c0 * 32 + lane];
                    float4 p1 = X4[(size_t)c1 * 32 + lane];
                    float4 p2 = X4[(size_t)c2 * 32 + lane];
                    float4 p3 = X4[(size_t)c3 * 32 + lane];
                    GFMA(acc, v0, p0); GFMA(acc, v1, p1);
                    GFMA(acc, v2, p2); GFMA(acc, v3, p3);
                }
                for (; e < end; ++e) {
                    int c = cols[e]; float v = vals[e];
                    float4 p = X4[(size_t)c * 32 + lane];
                    GFMA(acc, v, p);
                }
            }
            float4 h = H4[(size_t)r * 32 + lane];
            acc.x = fmaf(oma, acc.x, alpha * h.x);
            acc.y = fmaf(oma, acc.y, alpha * h.y);
            acc.z = fmaf(oma, acc.z, alpha * h.z);
            acc.w = fmaf(oma, acc.w, alpha * h.w);
        }
        uint32_t h01 = pack_bf16x2(acc.x, acc.y);
        uint32_t h23 = pack_bf16x2(acc.z, acc.w);
        float l0 = acc.x - __uint_as_float(h01 << 16);
        float l1 = acc.y - __uint_as_float(h01 & 0xffff0000u);
        float l2 = acc.z - __uint_as_float(h23 << 16);
        float l3 = acc.w - __uint_as_float(h23 & 0xffff0000u);
        uint32_t q01 = pack_bf16x2(l0, l1);
        uint32_t q23 = pack_bf16x2(l2, l3);
        uint32_t off = (uint32_t)(rr * SSTRB + lane * 8);
        asm volatile("st.shared.v2.b32 [%0], {%1, %2};"
                     :: "r"(smb + SM_SHI + off), "r"(h01), "r"(h23) : "memory");
        asm volatile("st.shared.v2.b32 [%0], {%1, %2};"
                     :: "r"(smb + SM_SLO + off), "r"(q01), "r"(q23) : "memory");
    }
    __syncthreads();

    // ---- phase 2: 16 warps x (32x32) warp tiles; mma.sync bf16, 3 passes ----
    const int wm = (wid & 3) * 32;
    const int wn = (wid >> 2) * 32;
    const int quad = lane >> 3;
    const int l7 = lane & 7;
    const uint32_t aoff = (uint32_t)((((quad & 1) * 8) + l7) * SSTRB + (quad >> 1) * 16);
    const uint32_t boff = (uint32_t)((((quad >> 1) * 8) + l7) * SSTRB + (quad & 1) * 16);

    float acc[2][4][4];
    #pragma unroll
    for (int i = 0; i < 2; ++i)
        #pragma unroll
        for (int j = 0; j < 4; ++j)
            #pragma unroll
            for (int k = 0; k < 4; ++k) acc[i][j][k] = 0.f;

    #pragma unroll
    for (int pass = 0; pass < 3; ++pass) {
        const uint32_t Ab = smb + (pass == 2 ? SM_SLO : SM_SHI) + (uint32_t)(wm * SSTRB) + aoff;
        const uint32_t Bb = smb + (pass == 1 ? SM_BLO : SM_BHI) + (uint32_t)(wn * SSTRB) + boff;
        #pragma unroll
        for (int ks = 0; ks < 8; ++ks) {
            uint32_t a0[4], a1[4], b01[4], b23[4];
            LDSM_X4(a0, Ab + ks * 32);
            LDSM_X4(a1, Ab + ks * 32 + 16 * SSTRB);
            LDSM_X4(b01, Bb + ks * 32);
            LDSM_X4(b23, Bb + ks * 32 + 16 * SSTRB);
            MMA(acc[0][0], a0, b01[0], b01[1]);
            MMA(acc[0][1], a0, b01[2], b01[3]);
            MMA(acc[0][2], a0, b23[0], b23[1]);
            MMA(acc[0][3], a0, b23[2], b23[3]);
            MMA(acc[1][0], a1, b01[0], b01[1]);
            MMA(acc[1][1], a1, b01[2], b01[3]);
            MMA(acc[1][2], a1, b23[0], b23[1]);
            MMA(acc[1][3], a1, b23[2], b23[3]);
        }
    }

    // ---- epilogue: + x residual ----
    const int g = lane >> 2, tig = lane & 3;
    #pragma unroll
    for (int mt = 0; mt < 2; ++mt) {
        #pragma unroll
        for (int half = 0; half < 2; ++half) {
            int r = rowBase + wm + mt * 16 + half * 8 + g;
            if (r < N) {
                const float2* Xr = (const float2*)x + (size_t)r * 64;
                float2* Or = (float2*)out + (size_t)r * 64;
                #pragma unroll
                for (int nt = 0; nt < 4; ++nt) {
                    int cp = (wn >> 1) + nt * 4 + tig;
                    float2 xv = Xr[cp];
                    float2 o;
                    o.x = acc[mt][nt][half * 2 + 0] + xv.x;
                    o.y = acc[mt][nt][half * 2 + 1] + xv.y;
                    Or[cp] = o;
                }
            }
        }
    }
}

extern "C" void kernel_launch(void* const* d_in, const int* in_sizes, int n_in,
                              void* d_out, int out_size) {
    const float* x     = (const float*)d_in[0];
    const float* h0    = (const float*)d_in[1];
    const float* W     = (const float*)d_in[2];
    const float* lamda = (const float*)d_in[3];
    const float* alpha = (const float*)d_in[4];
    const int*   arows = (const int*)d_in[5];
    const int*   acols = (const int*)d_in[6];
    const float* avals = (const float*)d_in[7];
    const int*   li    = (n_in > 8) ? (const int*)d_in[8] : nullptr;

    const int N = in_sizes[0] / D;
    const int E = in_sizes[5];

    prolog_kernel<<<(D * D / 2 + 511) / 512, 512>>>(W, lamda, li);

    (void)cudaFuncSetAttribute(gcn_fused_kernel,
                               cudaFuncAttributeMaxDynamicSharedMemorySize, SM_TOTAL);
    gcn_fused_kernel<<<(N + TILE_ROWS - 1) / TILE_ROWS, THREADS, SM_TOTAL>>>(
        x, h0, arows, acols, avals, alpha, (float*)d_out, N, E);
}